// round 11
// baseline (speedup 1.0000x reference)
#include <cuda_runtime.h>
#include <cuda_fp16.h>
#include <cstdint>

#define P_DROP   0.1f
#define ALPHA_F  0.1f
#define NUM_HOPS 10

// Fixed problem capacities (N=100000, E=3200000, IN=512, HID=64, OUT=64)
#define MAXN   100352
#define MAXE   3200000
#define MAXNH  6400000    // N*HID / N*OUT

// exact integer form of  (float)((bits>>9) * 2^-23) < 0.9f
#define KEEP_BITS_THRESH 3865470464u

// ---------------- static device scratch (no allocations allowed) ----------------
__device__ float              g_H[MAXNH];
__device__ float              g_Z0[MAXNH];    // fp32 Z0 (alpha anchor + final)
__device__ __half             g_Zh0[MAXNH];   // half Z0 (hop 0 gather input)
__device__ __half             g_Zha[MAXNH];   // ping
__device__ __half             g_Zhb[MAXNH];   // pong
__device__ int                g_cnt[MAXN];
__device__ int                g_rowptr[MAXN + 1];
__device__ int                g_fill[MAXN];
// packed per-CSR-position edge record: lo32 = col | (10-bit hop keep-mask << 22), hi32 = f32 weight
__device__ unsigned long long g_cw[MAXE];

// ---------------- packed f32x2 helpers (Blackwell FFMA2 path, PTX-only) ----------------
__device__ __forceinline__ void ffma2(unsigned long long& d, unsigned long long a,
                                      unsigned long long b) {
    asm("fma.rn.f32x2 %0, %1, %2, %3;" : "=l"(d) : "l"(a), "l"(b), "l"(d));
}
__device__ __forceinline__ unsigned long long packf2(float lo, float hi) {
    unsigned long long r;
    asm("mov.b64 %0, {%1, %2};" : "=l"(r) : "f"(lo), "f"(hi));
    return r;
}
__device__ __forceinline__ void unpackf2(float& lo, float& hi, unsigned long long v) {
    asm("mov.b64 {%0, %1}, %2;" : "=f"(lo), "=f"(hi) : "l"(v));
}

// ---------------- threefry-2x32 (JAX-exact, 20 rounds) ----------------
__host__ __device__ __forceinline__ void tf_block(unsigned k0, unsigned k1,
                                                  unsigned x0, unsigned x1,
                                                  unsigned& o0, unsigned& o1) {
    unsigned k2 = k0 ^ k1 ^ 0x1BD11BDAu;
    x0 += k0; x1 += k1;
#define TF_R(r) { x0 += x1; x1 = (x1 << (r)) | (x1 >> (32 - (r))); x1 ^= x0; }
    TF_R(13) TF_R(15) TF_R(26) TF_R(6)
    x0 += k1; x1 += k2 + 1u;
    TF_R(17) TF_R(29) TF_R(16) TF_R(24)
    x0 += k2; x1 += k0 + 2u;
    TF_R(13) TF_R(15) TF_R(26) TF_R(6)
    x0 += k0; x1 += k1 + 3u;
    TF_R(17) TF_R(29) TF_R(16) TF_R(24)
    x0 += k1; x1 += k2 + 4u;
    TF_R(13) TF_R(15) TF_R(26) TF_R(6)
    x0 += k2; x1 += k0 + 5u;
#undef TF_R
    o0 = x0; o1 = x1;
}

__device__ __forceinline__ unsigned tf_bits(unsigned k0, unsigned k1, unsigned lo) {
    unsigned a, b;
    tf_block(k0, k1, 0u, lo, a, b);
    return a ^ b;
}

__device__ __forceinline__ bool tf_keep(unsigned bits) {
    return bits < KEEP_BITS_THRESH;
}

struct HopKeys { unsigned a[NUM_HOPS]; unsigned b[NUM_HOPS]; };

// ---------------- CSR build ----------------
__global__ void zero_cnt_kernel(int n) {
    int i = blockIdx.x * blockDim.x + threadIdx.x;
    if (i < n) g_cnt[i] = 0;
}

__global__ void hist_kernel(const int* __restrict__ index, int E) {
    int e = blockIdx.x * blockDim.x + threadIdx.x;
    if (e < E) atomicAdd(&g_cnt[index[e]], 1);   // index[0..E) = row
}

__global__ void scan_kernel(int N, int E) {
    __shared__ int sm[1024];
    int t = threadIdx.x;
    int chunk = (N + 1023) >> 10;
    int beg = t * chunk; if (beg > N) beg = N;
    int end = beg + chunk; if (end > N) end = N;
    int s = 0;
    for (int i = beg; i < end; i++) s += g_cnt[i];
    sm[t] = s;
    __syncthreads();
    for (int off = 1; off < 1024; off <<= 1) {
        int v = (t >= off) ? sm[t - off] : 0;
        __syncthreads();
        sm[t] += v;
        __syncthreads();
    }
    int run = sm[t] - s;   // exclusive prefix
    for (int i = beg; i < end; i++) {
        g_rowptr[i] = run;
        g_fill[i]   = run;
        run += g_cnt[i];
    }
    if (t == 1023) g_rowptr[N] = E;
}

// ---------------- fused scatter + gemm1 ----------------
// Blocks [0, gemmBlocks):        gemm1 (fused X-dropout -> GEMM+relu -> H-dropout)
// Blocks [gemmBlocks, +scatBl):  CSR scatter + 10-hop edge masks + weight pack
// The two halves are independent; fusing them overlaps scatter's ALU-saturated
// hashing with the GEMM's FMA-pipe work inside one launch.
#define BM 64
#define BN 64
#define BK 32

__device__ __forceinline__ void scatter_body(int bid,
                                             const int* __restrict__ index,
                                             const float* __restrict__ value, int E,
                                             const HopKeys& hk,
                                             float invkeep, float onemA) {
    int e = bid * 256 + threadIdx.x;
    if (e >= E) return;
    int r = index[e];
    unsigned c = (unsigned)index[E + e];
    unsigned mask = 0;
#pragma unroll
    for (int h = 0; h < NUM_HOPS; h++) {
        unsigned bits = tf_bits(hk.a[h], hk.b[h], (unsigned)e);
        if (tf_keep(bits)) mask |= (1u << h);
    }
    float wk = onemA * (value[e] * invkeep);   // (1-alpha) * value/keep
    unsigned long long pk =
        ((unsigned long long)__float_as_uint(wk) << 32) |
        (unsigned long long)(c | (mask << 22));
    int pos = atomicAdd(&g_fill[r], 1);
    g_cw[pos] = pk;
}

__global__ __launch_bounds__(256) void fused_scatter_gemm1_kernel(
    const int* __restrict__ index, const float* __restrict__ value, int E,
    HopKeys hk, float onemA,
    const float* __restrict__ X, const float* __restrict__ W,
    const float* __restrict__ bias, int Nrows, int K,
    unsigned ka0, unsigned ka1, unsigned kh0, unsigned kh1,
    float invkeep, int gemmBlocks) {
    __shared__ float As[BM][BK + 1];
    __shared__ float Ws[BK][BN];

    if ((int)blockIdx.x >= gemmBlocks) {
        scatter_body((int)blockIdx.x - gemmBlocks, index, value, E, hk, invkeep, onemA);
        return;
    }

    // ---- gemm1 body ----
    int tid = threadIdx.x;
    int tx = tid & 15, ty = tid >> 4;
    int rowBase = blockIdx.x * BM;
    unsigned long long acc2[4][2];
#pragma unroll
    for (int i = 0; i < 4; i++) { acc2[i][0] = 0ull; acc2[i][1] = 0ull; }

    for (int k0 = 0; k0 < K; k0 += BK) {
#pragma unroll
        for (int l = 0; l < 2; l++) {
            int idx = tid + l * 256;           // A tile 64x32 = 512 float4 slots
            int r = idx >> 3, c4 = idx & 7;
            int gr = rowBase + r;
            float4 v = make_float4(0.f, 0.f, 0.f, 0.f);
            if (gr < Nrows) {
                v = *(const float4*)&X[(size_t)gr * K + k0 + c4 * 4];
                unsigned eb = (unsigned)gr * (unsigned)K + (unsigned)(k0 + c4 * 4);
                v.x = tf_keep(tf_bits(ka0, ka1, eb + 0)) ? v.x * invkeep : 0.f;
                v.y = tf_keep(tf_bits(ka0, ka1, eb + 1)) ? v.y * invkeep : 0.f;
                v.z = tf_keep(tf_bits(ka0, ka1, eb + 2)) ? v.z * invkeep : 0.f;
                v.w = tf_keep(tf_bits(ka0, ka1, eb + 3)) ? v.w * invkeep : 0.f;
            }
            As[r][c4 * 4 + 0] = v.x; As[r][c4 * 4 + 1] = v.y;
            As[r][c4 * 4 + 2] = v.z; As[r][c4 * 4 + 3] = v.w;
        }
#pragma unroll
        for (int l = 0; l < 2; l++) {
            int idx = tid + l * 256;           // W tile 32x64
            int r = idx >> 4, c4 = idx & 15;
            float4 v = *(const float4*)&W[(size_t)(k0 + r) * BN + c4 * 4];
            *(float4*)&Ws[r][c4 * 4] = v;
        }
        __syncthreads();
#pragma unroll
        for (int k = 0; k < BK; k++) {
            float4 w = *(float4*)&Ws[k][tx * 4];
            unsigned long long w01 = packf2(w.x, w.y);
            unsigned long long w23 = packf2(w.z, w.w);
#pragma unroll
            for (int i = 0; i < 4; i++) {
                float a = As[ty * 4 + i][k];
                unsigned long long aa = packf2(a, a);
                ffma2(acc2[i][0], aa, w01);
                ffma2(acc2[i][1], aa, w23);
            }
        }
        __syncthreads();
    }
    float4 bv = *(const float4*)&bias[tx * 4];
#pragma unroll
    for (int i = 0; i < 4; i++) {
        int gr = rowBase + ty * 4 + i;
        if (gr < Nrows) {
            float4 o;
            unpackf2(o.x, o.y, acc2[i][0]);
            unpackf2(o.z, o.w, acc2[i][1]);
            o.x += bv.x; o.y += bv.y; o.z += bv.z; o.w += bv.w;
            o.x = fmaxf(o.x, 0.f); o.y = fmaxf(o.y, 0.f);
            o.z = fmaxf(o.z, 0.f); o.w = fmaxf(o.w, 0.f);
            unsigned hb = (unsigned)gr * 64u + (unsigned)(tx * 4);
            o.x = tf_keep(tf_bits(kh0, kh1, hb + 0)) ? o.x * invkeep : 0.f;
            o.y = tf_keep(tf_bits(kh0, kh1, hb + 1)) ? o.y * invkeep : 0.f;
            o.z = tf_keep(tf_bits(kh0, kh1, hb + 2)) ? o.z * invkeep : 0.f;
            o.w = tf_keep(tf_bits(kh0, kh1, hb + 3)) ? o.w * invkeep : 0.f;
            *(float4*)&g_H[(size_t)gr * BN + tx * 4] = o;
        }
    }
}

// ---------------- gemm2: H @ W2 + b2 -> g_Z0 (fp32) and g_Zh0 (half) ----------------
__global__ __launch_bounds__(256) void gemm2_kernel(const float* __restrict__ W,
                                                    const float* __restrict__ bias,
                                                    int Nrows, int K) {
    const float* __restrict__ A = g_H;
    __shared__ float As[BM][BK + 1];
    __shared__ float Ws[BK][BN];
    int tid = threadIdx.x;
    int tx = tid & 15, ty = tid >> 4;
    int rowBase = blockIdx.x * BM;
    unsigned long long acc2[4][2];
#pragma unroll
    for (int i = 0; i < 4; i++) { acc2[i][0] = 0ull; acc2[i][1] = 0ull; }

    for (int k0 = 0; k0 < K; k0 += BK) {
#pragma unroll
        for (int l = 0; l < 2; l++) {
            int idx = tid + l * 256;
            int r = idx >> 3, c4 = idx & 7;
            int gr = rowBase + r;
            float4 v = make_float4(0.f, 0.f, 0.f, 0.f);
            if (gr < Nrows) v = *(const float4*)&A[(size_t)gr * K + k0 + c4 * 4];
            As[r][c4 * 4 + 0] = v.x; As[r][c4 * 4 + 1] = v.y;
            As[r][c4 * 4 + 2] = v.z; As[r][c4 * 4 + 3] = v.w;
        }
#pragma unroll
        for (int l = 0; l < 2; l++) {
            int idx = tid + l * 256;
            int r = idx >> 4, c4 = idx & 15;
            float4 v = *(const float4*)&W[(size_t)(k0 + r) * BN + c4 * 4];
            *(float4*)&Ws[r][c4 * 4] = v;
        }
        __syncthreads();
#pragma unroll
        for (int k = 0; k < BK; k++) {
            float4 w = *(float4*)&Ws[k][tx * 4];
            unsigned long long w01 = packf2(w.x, w.y);
            unsigned long long w23 = packf2(w.z, w.w);
#pragma unroll
            for (int i = 0; i < 4; i++) {
                float a = As[ty * 4 + i][k];
                unsigned long long aa = packf2(a, a);
                ffma2(acc2[i][0], aa, w01);
                ffma2(acc2[i][1], aa, w23);
            }
        }
        __syncthreads();
    }
    float4 bv = *(const float4*)&bias[tx * 4];
#pragma unroll
    for (int i = 0; i < 4; i++) {
        int gr = rowBase + ty * 4 + i;
        if (gr < Nrows) {
            float4 o;
            unpackf2(o.x, o.y, acc2[i][0]);
            unpackf2(o.z, o.w, acc2[i][1]);
            o.x += bv.x; o.y += bv.y; o.z += bv.z; o.w += bv.w;
            *(float4*)&g_Z0[(size_t)gr * BN + tx * 4] = o;
            __half2 h01 = __floats2half2_rn(o.x, o.y);
            __half2 h23 = __floats2half2_rn(o.z, o.w);
            uint2 hp;
            hp.x = *(unsigned*)&h01;
            hp.y = *(unsigned*)&h23;
            *(uint2*)&g_Zh0[(size_t)gr * BN + tx * 4] = hp;
        }
    }
}

// ---------------- propagation hop: half Z gather, fp32 accumulate, exact 16^-h scaling ----------------
// Dropped edges redirect their gather to row 0 (L1-resident hot line -> ~no LTS
// traffic) with ww=0, keeping the loads unconditional and batchable.
__global__ __launch_bounds__(256) void hop_kernel(int hop, float* __restrict__ dout,
                                                  int Nrows, float mulA, float mulB) {
    const __half* __restrict__ Zin =
        (hop == 0) ? g_Zh0 : ((hop & 1) ? g_Zha : g_Zhb);
    __half* __restrict__ Zout = (hop & 1) ? g_Zhb : g_Zha;
    bool isLast = (hop == NUM_HOPS - 1);

    int gw   = (int)((blockIdx.x * (unsigned)blockDim.x + threadIdx.x) >> 5);
    int half_id = (threadIdx.x >> 4) & 1;
    int l    = threadIdx.x & 15;
    int r    = gw * 2 + half_id;

    int s = 0, e = 0;
    if (r < Nrows) { s = g_rowptr[r]; e = g_rowptr[r + 1]; }
    unsigned sh = 22u + (unsigned)hop;
    float ax = 0.f, ay = 0.f, az = 0.f, aw = 0.f;
#pragma unroll 4
    for (int j = s; j < e; j++) {
        unsigned long long pk = __ldg(&g_cw[j]);
        unsigned cw = (unsigned)pk;
        bool keep = (cw >> sh) & 1u;
        unsigned c = keep ? (cw & 0x3FFFFFu) : 0u;   // dropped -> hot row 0
        float ww = keep ? __uint_as_float((unsigned)(pk >> 32)) : 0.0f;
        uint2 raw = *(const uint2*)&Zin[(size_t)c * 64 + l * 4];
        float2 z01 = __half22float2(*(const __half2*)&raw.x);
        float2 z23 = __half22float2(*(const __half2*)&raw.y);
        ax = fmaf(ww, z01.x, ax);
        ay = fmaf(ww, z01.y, ay);
        az = fmaf(ww, z23.x, az);
        aw = fmaf(ww, z23.y, aw);
    }
    if (r < Nrows) {
        float4 z0 = *(const float4*)&g_Z0[(size_t)r * 64 + l * 4];
        float ox = ax * mulA + mulB * z0.x;
        float oy = ay * mulA + mulB * z0.y;
        float oz = az * mulA + mulB * z0.z;
        float ow = aw * mulA + mulB * z0.w;
        if (isLast) {
            float4 o = make_float4(ox, oy, oz, ow);
            *(float4*)&dout[(size_t)r * 64 + l * 4] = o;
        } else {
            __half2 h01 = __floats2half2_rn(ox, oy);
            __half2 h23 = __floats2half2_rn(oz, ow);
            uint2 hp;
            hp.x = *(unsigned*)&h01;
            hp.y = *(unsigned*)&h23;
            *(uint2*)&Zout[(size_t)r * 64 + l * 4] = hp;
        }
    }
}

// ---------------- host ----------------
extern "C" void kernel_launch(void* const* d_in, const int* in_sizes, int n_in,
                              void* d_out, int out_size) {
    const int*   index = (const int*)d_in[0];
    const float* value = (const float*)d_in[1];
    // Optional scalar "n" may appear as a size-1 input at slot 2.
    int base = (n_in >= 8 && in_sizes[2] == 1) ? 3 : 2;
    const float* X  = (const float*)d_in[base + 0];
    const float* W1 = (const float*)d_in[base + 1];
    const float* b1 = (const float*)d_in[base + 2];
    const float* W2 = (const float*)d_in[base + 3];
    const float* b2 = (const float*)d_in[base + 4];

    int E   = in_sizes[1];
    int HID = in_sizes[base + 2];
    int OUT = in_sizes[base + 4];
    int IN  = in_sizes[base + 1] / HID;
    int N   = in_sizes[base + 0] / IN;
    (void)out_size; (void)OUT;

    // ---- derive JAX keys on host (key(42), fold-like split, fold_in) ----
    unsigned rk0 = 0u, rk1 = 42u;
    unsigned kx0, kx1, kh0, kh1, ke0, ke1;
    tf_block(rk0, rk1, 0u, 0u, kx0, kx1);   // split[0]
    tf_block(rk0, rk1, 0u, 1u, kh0, kh1);   // split[1]
    tf_block(rk0, rk1, 0u, 2u, ke0, ke1);   // split[2]
    HopKeys hk;
    for (unsigned h = 0; h < NUM_HOPS; h++)
        tf_block(ke0, ke1, 0u, h, hk.a[h], hk.b[h]);   // fold_in(ke, h)

    const float invkeep = 1.0f / (1.0f - P_DROP);
    const float onemA   = 1.0f - ALPHA_F;

    const int T = 256;

    // ---- CSR counts + prefix ----
    zero_cnt_kernel<<<(N + T - 1) / T, T>>>(N);
    hist_kernel<<<(E + T - 1) / T, T>>>(index, E);
    scan_kernel<<<1, 1024>>>(N, E);

    // ---- fused: scatter (edge masks + weights) || gemm1 ----
    int gemmBlocks = (N + BM - 1) / BM;
    int scatBlocks = (E + T - 1) / T;
    fused_scatter_gemm1_kernel<<<gemmBlocks + scatBlocks, T>>>(
        index, value, E, hk, onemA,
        X, W1, b1, N, IN, kx0, kx1, kh0, kh1, invkeep, gemmBlocks);

    // ---- gemm2 ----
    gemm2_kernel<<<(N + BM - 1) / BM, T>>>(W2, b2, N, HID);

    // ---- 10 propagation hops, half Z storage with exact 2^-4h scaling ----
    int warpsNeeded = (N + 1) / 2;
    int hopBlocks = (warpsNeeded * 32 + T - 1) / T;
    for (int h = 0; h < NUM_HOPS; h++) {
        float mulA, mulB;
        if (h == NUM_HOPS - 1) {
            mulA = ldexpf(1.0f, 4 * (NUM_HOPS - 1));   // 16^9, exact
            mulB = ALPHA_F;
        } else {
            mulA = 0.0625f;                            // 1/16, exact
            mulB = ALPHA_F * ldexpf(1.0f, -4 * (h + 1));
        }
        hop_kernel<<<hopBlocks, T>>>(h, (float*)d_out, N, mulA, mulB);
    }
}

// round 15
// speedup vs baseline: 1.0193x; 1.0193x over previous
#include <cuda_runtime.h>
#include <cuda_fp16.h>
#include <cstdint>

#define P_DROP   0.1f
#define ALPHA_F  0.1f
#define NUM_HOPS 10

// Fixed problem capacities (N=100000, E=3200000, IN=512, HID=64, OUT=64)
#define MAXN   100352
#define MAXE   3200000
#define MAXNH  6400000    // N*HID / N*OUT

// exact integer form of  (float)((bits>>9) * 2^-23) < 0.9f
#define KEEP_BITS_THRESH 3865470464u

// ---------------- static device scratch (no allocations allowed) ----------------
__device__ float              g_H[MAXNH];
__device__ float              g_Z0[MAXNH];    // fp32 Z0 (alpha anchor + final)
__device__ __half             g_Zh0[MAXNH];   // half Z0 (hop 0 gather input)
__device__ __half             g_Zha[MAXNH];   // ping
__device__ __half             g_Zhb[MAXNH];   // pong
__device__ int                g_cnt[MAXN];
__device__ int                g_rowptr[MAXN + 1];
__device__ int                g_fill[MAXN];
// packed per-CSR-position edge record: lo32 = col | (10-bit hop keep-mask << 22), hi32 = f32 weight
__device__ unsigned long long g_cw[MAXE];

// ---------------- packed f32x2 helpers (Blackwell FFMA2 path, PTX-only) ----------------
__device__ __forceinline__ void ffma2(unsigned long long& d, unsigned long long a,
                                      unsigned long long b) {
    asm("fma.rn.f32x2 %0, %1, %2, %3;" : "=l"(d) : "l"(a), "l"(b), "l"(d));
}
__device__ __forceinline__ unsigned long long packf2(float lo, float hi) {
    unsigned long long r;
    asm("mov.b64 %0, {%1, %2};" : "=l"(r) : "f"(lo), "f"(hi));
    return r;
}
__device__ __forceinline__ void unpackf2(float& lo, float& hi, unsigned long long v) {
    asm("mov.b64 {%0, %1}, %2;" : "=f"(lo), "=f"(hi) : "l"(v));
}

// ---------------- threefry-2x32 (JAX-exact, 20 rounds) ----------------
__host__ __device__ __forceinline__ void tf_block(unsigned k0, unsigned k1,
                                                  unsigned x0, unsigned x1,
                                                  unsigned& o0, unsigned& o1) {
    unsigned k2 = k0 ^ k1 ^ 0x1BD11BDAu;
    x0 += k0; x1 += k1;
#define TF_R(r) { x0 += x1; x1 = (x1 << (r)) | (x1 >> (32 - (r))); x1 ^= x0; }
    TF_R(13) TF_R(15) TF_R(26) TF_R(6)
    x0 += k1; x1 += k2 + 1u;
    TF_R(17) TF_R(29) TF_R(16) TF_R(24)
    x0 += k2; x1 += k0 + 2u;
    TF_R(13) TF_R(15) TF_R(26) TF_R(6)
    x0 += k0; x1 += k1 + 3u;
    TF_R(17) TF_R(29) TF_R(16) TF_R(24)
    x0 += k1; x1 += k2 + 4u;
    TF_R(13) TF_R(15) TF_R(26) TF_R(6)
    x0 += k2; x1 += k0 + 5u;
#undef TF_R
    o0 = x0; o1 = x1;
}

__device__ __forceinline__ unsigned tf_bits(unsigned k0, unsigned k1, unsigned lo) {
    unsigned a, b;
    tf_block(k0, k1, 0u, lo, a, b);
    return a ^ b;
}

__device__ __forceinline__ bool tf_keep(unsigned bits) {
    return bits < KEEP_BITS_THRESH;
}

struct HopKeys { unsigned a[NUM_HOPS]; unsigned b[NUM_HOPS]; };

// ---------------- CSR build ----------------
__global__ void zero_cnt_kernel(int n) {
    int i = blockIdx.x * blockDim.x + threadIdx.x;
    if (i < n) g_cnt[i] = 0;
}

__global__ void hist_kernel(const int* __restrict__ index, int E) {
    int e = blockIdx.x * blockDim.x + threadIdx.x;
    if (e < E) atomicAdd(&g_cnt[index[e]], 1);   // index[0..E) = row
}

__global__ void scan_kernel(int N, int E) {
    __shared__ int sm[1024];
    int t = threadIdx.x;
    int chunk = (N + 1023) >> 10;
    int beg = t * chunk; if (beg > N) beg = N;
    int end = beg + chunk; if (end > N) end = N;
    int s = 0;
    for (int i = beg; i < end; i++) s += g_cnt[i];
    sm[t] = s;
    __syncthreads();
    for (int off = 1; off < 1024; off <<= 1) {
        int v = (t >= off) ? sm[t - off] : 0;
        __syncthreads();
        sm[t] += v;
        __syncthreads();
    }
    int run = sm[t] - s;   // exclusive prefix
    for (int i = beg; i < end; i++) {
        g_rowptr[i] = run;
        g_fill[i]   = run;
        run += g_cnt[i];
    }
    if (t == 1023) g_rowptr[N] = E;
}

// Fused: CSR scatter + 10-hop edge-dropout masks + edge weight, one packed 8B store.
__global__ void scatter_kernel(const int* __restrict__ index,
                               const float* __restrict__ value, int E, HopKeys hk,
                               float invkeep, float onemA) {
    int e = blockIdx.x * blockDim.x + threadIdx.x;
    if (e >= E) return;
    int r = index[e];
    unsigned c = (unsigned)index[E + e];
    unsigned mask = 0;
#pragma unroll
    for (int h = 0; h < NUM_HOPS; h++) {
        unsigned bits = tf_bits(hk.a[h], hk.b[h], (unsigned)e);
        if (tf_keep(bits)) mask |= (1u << h);
    }
    float wk = onemA * (value[e] * invkeep);   // (1-alpha) * value/keep
    unsigned long long pk =
        ((unsigned long long)__float_as_uint(wk) << 32) |
        (unsigned long long)(c | (mask << 22));
    int pos = atomicAdd(&g_fill[r], 1);
    g_cw[pos] = pk;
}

// ---------------- fp32 SIMT GEMM with fused dropout, FFMA2 inner loop ----------------
// MODE 0: A = dropout_ka(X) on the fly; epilogue: relu then dropout_kh; -> g_H
// MODE 1: A = g_H; plain epilogue; -> g_Z0 (fp32) AND g_Zh0 (half)
#define BM 64
#define BN 64
#define BK 32
template<int MODE>
__global__ __launch_bounds__(256) void gemm_kernel(const float* __restrict__ Ain,
                                                   const float* __restrict__ W,
                                                   const float* __restrict__ bias,
                                                   int Nrows, int K,
                                                   unsigned ka0, unsigned ka1,
                                                   unsigned kh0, unsigned kh1,
                                                   float invkeep) {
    const float* __restrict__ A = (MODE == 0) ? Ain : g_H;
    float* __restrict__ O       = (MODE == 0) ? g_H : g_Z0;
    __shared__ float As[BM][BK + 1];
    __shared__ float Ws[BK][BN];
    int tid = threadIdx.x;
    int tx = tid & 15, ty = tid >> 4;
    int rowBase = blockIdx.x * BM;
    unsigned long long acc2[4][2];
#pragma unroll
    for (int i = 0; i < 4; i++) { acc2[i][0] = 0ull; acc2[i][1] = 0ull; }

    for (int k0 = 0; k0 < K; k0 += BK) {
#pragma unroll
        for (int l = 0; l < 2; l++) {
            int idx = tid + l * 256;           // A tile 64x32 = 512 float4 slots
            int r = idx >> 3, c4 = idx & 7;
            int gr = rowBase + r;
            float4 v = make_float4(0.f, 0.f, 0.f, 0.f);
            if (gr < Nrows) {
                v = *(const float4*)&A[(size_t)gr * K + k0 + c4 * 4];
                if (MODE == 0) {
                    unsigned eb = (unsigned)gr * (unsigned)K + (unsigned)(k0 + c4 * 4);
                    v.x = tf_keep(tf_bits(ka0, ka1, eb + 0)) ? v.x * invkeep : 0.f;
                    v.y = tf_keep(tf_bits(ka0, ka1, eb + 1)) ? v.y * invkeep : 0.f;
                    v.z = tf_keep(tf_bits(ka0, ka1, eb + 2)) ? v.z * invkeep : 0.f;
                    v.w = tf_keep(tf_bits(ka0, ka1, eb + 3)) ? v.w * invkeep : 0.f;
                }
            }
            As[r][c4 * 4 + 0] = v.x; As[r][c4 * 4 + 1] = v.y;
            As[r][c4 * 4 + 2] = v.z; As[r][c4 * 4 + 3] = v.w;
        }
#pragma unroll
        for (int l = 0; l < 2; l++) {
            int idx = tid + l * 256;           // W tile 32x64
            int r = idx >> 4, c4 = idx & 15;
            float4 v = *(const float4*)&W[(size_t)(k0 + r) * BN + c4 * 4];
            *(float4*)&Ws[r][c4 * 4] = v;
        }
        __syncthreads();
#pragma unroll
        for (int k = 0; k < BK; k++) {
            float4 w = *(float4*)&Ws[k][tx * 4];
            unsigned long long w01 = packf2(w.x, w.y);
            unsigned long long w23 = packf2(w.z, w.w);
#pragma unroll
            for (int i = 0; i < 4; i++) {
                float a = As[ty * 4 + i][k];
                unsigned long long aa = packf2(a, a);
                ffma2(acc2[i][0], aa, w01);
                ffma2(acc2[i][1], aa, w23);
            }
        }
        __syncthreads();
    }
    float4 bv = *(const float4*)&bias[tx * 4];
#pragma unroll
    for (int i = 0; i < 4; i++) {
        int gr = rowBase + ty * 4 + i;
        if (gr < Nrows) {
            float4 o;
            unpackf2(o.x, o.y, acc2[i][0]);
            unpackf2(o.z, o.w, acc2[i][1]);
            o.x += bv.x; o.y += bv.y; o.z += bv.z; o.w += bv.w;
            if (MODE == 0) {
                o.x = fmaxf(o.x, 0.f); o.y = fmaxf(o.y, 0.f);
                o.z = fmaxf(o.z, 0.f); o.w = fmaxf(o.w, 0.f);
                unsigned hb = (unsigned)gr * 64u + (unsigned)(tx * 4);
                o.x = tf_keep(tf_bits(kh0, kh1, hb + 0)) ? o.x * invkeep : 0.f;
                o.y = tf_keep(tf_bits(kh0, kh1, hb + 1)) ? o.y * invkeep : 0.f;
                o.z = tf_keep(tf_bits(kh0, kh1, hb + 2)) ? o.z * invkeep : 0.f;
                o.w = tf_keep(tf_bits(kh0, kh1, hb + 3)) ? o.w * invkeep : 0.f;
            }
            *(float4*)&O[(size_t)gr * BN + tx * 4] = o;
            if (MODE == 1) {
                // half copy for the hop-0 gather
                __half2 h01 = __floats2half2_rn(o.x, o.y);
                __half2 h23 = __floats2half2_rn(o.z, o.w);
                uint2 hp;
                hp.x = *(unsigned*)&h01;
                hp.y = *(unsigned*)&h23;
                *(uint2*)&g_Zh0[(size_t)gr * BN + tx * 4] = hp;
            }
        }
    }
}

// ---------------- propagation hop: half Z gather, fp32 accumulate, exact 16^-h scaling ----------------
// Branch-free body: dropped edges contribute 0 via ww=0 (exact).  #pragma unroll 4
// lets ptxas front-batch 4 cw loads then 4 Z loads (MLP ~8 vs ~2 before).
__global__ __launch_bounds__(256) void hop_kernel(int hop, float* __restrict__ dout,
                                                  int Nrows, float mulA, float mulB) {
    const __half* __restrict__ Zin =
        (hop == 0) ? g_Zh0 : ((hop & 1) ? g_Zha : g_Zhb);
    __half* __restrict__ Zout = (hop & 1) ? g_Zhb : g_Zha;
    bool isLast = (hop == NUM_HOPS - 1);

    int gw   = (int)((blockIdx.x * (unsigned)blockDim.x + threadIdx.x) >> 5);
    int half_id = (threadIdx.x >> 4) & 1;
    int l    = threadIdx.x & 15;
    int r    = gw * 2 + half_id;

    int s = 0, e = 0;
    if (r < Nrows) { s = g_rowptr[r]; e = g_rowptr[r + 1]; }
    unsigned sh = 22u + (unsigned)hop;
    float ax = 0.f, ay = 0.f, az = 0.f, aw = 0.f;
#pragma unroll 4
    for (int j = s; j < e; j++) {
        unsigned long long pk = __ldg(&g_cw[j]);
        unsigned cw = (unsigned)pk;
        float ww = ((cw >> sh) & 1u) ? __uint_as_float((unsigned)(pk >> 32)) : 0.0f;
        uint2 raw = *(const uint2*)&Zin[(size_t)(cw & 0x3FFFFFu) * 64 + l * 4];
        float2 z01 = __half22float2(*(const __half2*)&raw.x);
        float2 z23 = __half22float2(*(const __half2*)&raw.y);
        ax = fmaf(ww, z01.x, ax);
        ay = fmaf(ww, z01.y, ay);
        az = fmaf(ww, z23.x, az);
        aw = fmaf(ww, z23.y, aw);
    }
    if (r < Nrows) {
        float4 z0 = *(const float4*)&g_Z0[(size_t)r * 64 + l * 4];
        float ox = ax * mulA + mulB * z0.x;
        float oy = ay * mulA + mulB * z0.y;
        float oz = az * mulA + mulB * z0.z;
        float ow = aw * mulA + mulB * z0.w;
        if (isLast) {
            float4 o = make_float4(ox, oy, oz, ow);
            *(float4*)&dout[(size_t)r * 64 + l * 4] = o;
        } else {
            __half2 h01 = __floats2half2_rn(ox, oy);
            __half2 h23 = __floats2half2_rn(oz, ow);
            uint2 hp;
            hp.x = *(unsigned*)&h01;
            hp.y = *(unsigned*)&h23;
            *(uint2*)&Zout[(size_t)r * 64 + l * 4] = hp;
        }
    }
}

// ---------------- host ----------------
extern "C" void kernel_launch(void* const* d_in, const int* in_sizes, int n_in,
                              void* d_out, int out_size) {
    const int*   index = (const int*)d_in[0];
    const float* value = (const float*)d_in[1];
    // Optional scalar "n" may appear as a size-1 input at slot 2.
    int base = (n_in >= 8 && in_sizes[2] == 1) ? 3 : 2;
    const float* X  = (const float*)d_in[base + 0];
    const float* W1 = (const float*)d_in[base + 1];
    const float* b1 = (const float*)d_in[base + 2];
    const float* W2 = (const float*)d_in[base + 3];
    const float* b2 = (const float*)d_in[base + 4];

    int E   = in_sizes[1];
    int HID = in_sizes[base + 2];
    int OUT = in_sizes[base + 4];
    int IN  = in_sizes[base + 1] / HID;
    int N   = in_sizes[base + 0] / IN;
    (void)out_size; (void)OUT;

    // ---- derive JAX keys on host (key(42), fold-like split, fold_in) ----
    unsigned rk0 = 0u, rk1 = 42u;
    unsigned kx0, kx1, kh0, kh1, ke0, ke1;
    tf_block(rk0, rk1, 0u, 0u, kx0, kx1);   // split[0]
    tf_block(rk0, rk1, 0u, 1u, kh0, kh1);   // split[1]
    tf_block(rk0, rk1, 0u, 2u, ke0, ke1);   // split[2]
    HopKeys hk;
    for (unsigned h = 0; h < NUM_HOPS; h++)
        tf_block(ke0, ke1, 0u, h, hk.a[h], hk.b[h]);   // fold_in(ke, h)

    const float invkeep = 1.0f / (1.0f - P_DROP);
    const float onemA   = 1.0f - ALPHA_F;

    const int T = 256;

    // ---- CSR build fused with edge-dropout masks + weights ----
    zero_cnt_kernel<<<(N + T - 1) / T, T>>>(N);
    hist_kernel<<<(E + T - 1) / T, T>>>(index, E);
    scan_kernel<<<1, 1024>>>(N, E);
    scatter_kernel<<<(E + T - 1) / T, T>>>(index, value, E, hk, invkeep, onemA);

    // ---- MLP: gemm1 (fused dropout-in + relu + dropout-out) -> gemm2 ----
    gemm_kernel<0><<<(N + BM - 1) / BM, 256>>>(X, W1, b1, N, IN,
                                               kx0, kx1, kh0, kh1, invkeep);
    gemm_kernel<1><<<(N + BM - 1) / BM, 256>>>(X, W2, b2, N, HID,
                                               0u, 0u, 0u, 0u, invkeep);

    // ---- 10 propagation hops, half Z storage with exact 2^-4h scaling ----
    int warpsNeeded = (N + 1) / 2;
    int hopBlocks = (warpsNeeded * 32 + T - 1) / T;
    for (int h = 0; h < NUM_HOPS; h++) {
        float mulA, mulB;
        if (h == NUM_HOPS - 1) {
            mulA = ldexpf(1.0f, 4 * (NUM_HOPS - 1));   // 16^9, exact
            mulB = ALPHA_F;
        } else {
            mulA = 0.0625f;                            // 1/16, exact
            mulB = ALPHA_F * ldexpf(1.0f, -4 * (h + 1));
        }
        hop_kernel<<<hopBlocks, T>>>(h, (float*)d_out, N, mulA, mulB);
    }
}

// round 16
// speedup vs baseline: 1.4543x; 1.4268x over previous
#include <cuda_runtime.h>
#include <cuda_fp16.h>
#include <cstdint>

#define P_DROP   0.1f
#define ALPHA_F  0.1f
#define NUM_HOPS 10

// Fixed problem capacities (N=100000, E=3200000, IN=512, HID=64, OUT=64)
#define MAXN   100352
#define MAXE   3200000
#define MAXNH  6400000    // N*HID / N*OUT

// exact integer form of  (float)((bits>>9) * 2^-23) < 0.9f
#define KEEP_BITS_THRESH 3865470464u

// ---------------- static device scratch (no allocations allowed) ----------------
__device__ float              g_H[MAXNH];
__device__ float              g_Z0[MAXNH];    // fp32 Z0 (alpha anchor + final)
__device__ __half             g_Zh0[MAXNH];   // half Z0 (hop 0 gather input)
__device__ __half             g_Zha[MAXNH];   // ping
__device__ __half             g_Zhb[MAXNH];   // pong
__device__ int                g_cnt[MAXN];
__device__ int                g_rowptr[MAXN + 1];
__device__ int                g_fill[MAXN];
__device__ int                g_bsum[128];
__device__ int                g_bpre[128];
// packed per-CSR-position edge record:
//   lo32 = col(17 bits) | e_low15 << 17
//   hi32 = e_high7 (bits [0:7)) | top-25-bits-of-fp32-weight (bits [7:32))
__device__ unsigned long long g_cw[MAXE];

// ---------------- packed f32x2 helpers (Blackwell FFMA2 path, PTX-only) ----------------
__device__ __forceinline__ void ffma2(unsigned long long& d, unsigned long long a,
                                      unsigned long long b) {
    asm("fma.rn.f32x2 %0, %1, %2, %3;" : "=l"(d) : "l"(a), "l"(b), "l"(d));
}
__device__ __forceinline__ unsigned long long packf2(float lo, float hi) {
    unsigned long long r;
    asm("mov.b64 %0, {%1, %2};" : "=l"(r) : "f"(lo), "f"(hi));
    return r;
}
__device__ __forceinline__ void unpackf2(float& lo, float& hi, unsigned long long v) {
    asm("mov.b64 {%0, %1}, %2;" : "=f"(lo), "=f"(hi) : "l"(v));
}

// ---------------- threefry-2x32 (JAX-exact, 20 rounds) ----------------
__host__ __device__ __forceinline__ void tf_block(unsigned k0, unsigned k1,
                                                  unsigned x0, unsigned x1,
                                                  unsigned& o0, unsigned& o1) {
    unsigned k2 = k0 ^ k1 ^ 0x1BD11BDAu;
    x0 += k0; x1 += k1;
#define TF_R(r) { x0 += x1; x1 = (x1 << (r)) | (x1 >> (32 - (r))); x1 ^= x0; }
    TF_R(13) TF_R(15) TF_R(26) TF_R(6)
    x0 += k1; x1 += k2 + 1u;
    TF_R(17) TF_R(29) TF_R(16) TF_R(24)
    x0 += k2; x1 += k0 + 2u;
    TF_R(13) TF_R(15) TF_R(26) TF_R(6)
    x0 += k0; x1 += k1 + 3u;
    TF_R(17) TF_R(29) TF_R(16) TF_R(24)
    x0 += k1; x1 += k2 + 4u;
    TF_R(13) TF_R(15) TF_R(26) TF_R(6)
    x0 += k2; x1 += k0 + 5u;
#undef TF_R
    o0 = x0; o1 = x1;
}

__device__ __forceinline__ unsigned tf_bits(unsigned k0, unsigned k1, unsigned lo) {
    unsigned a, b;
    tf_block(k0, k1, 0u, lo, a, b);
    return a ^ b;
}

__device__ __forceinline__ bool tf_keep(unsigned bits) {
    return bits < KEEP_BITS_THRESH;
}

// ---------------- CSR build ----------------
__global__ void zero_cnt_kernel(int n) {
    int i = blockIdx.x * blockDim.x + threadIdx.x;
    if (i < n) g_cnt[i] = 0;
}

__global__ void hist_kernel(const int* __restrict__ index, int E) {
    int e = blockIdx.x * blockDim.x + threadIdx.x;
    if (e < E) atomicAdd(&g_cnt[index[e]], 1);   // index[0..E) = row
}

// 3-phase parallel exclusive scan of g_cnt -> g_rowptr/g_fill
__global__ void scanA_kernel(int N) {
    __shared__ int red[256];
    int b = blockIdx.x;                    // 128 blocks
    int chunk = (N + 127) / 128;
    int beg = b * chunk;
    int end = beg + chunk; if (end > N) end = N;
    int s = 0;
    for (int i = beg + threadIdx.x; i < end; i += 256) s += g_cnt[i];
    red[threadIdx.x] = s;
    __syncthreads();
    for (int off = 128; off > 0; off >>= 1) {
        if ((int)threadIdx.x < off) red[threadIdx.x] += red[threadIdx.x + off];
        __syncthreads();
    }
    if (threadIdx.x == 0) g_bsum[b] = red[0];
}

__global__ void scanB_kernel(int N, int E) {
    __shared__ int sm[128];
    int t = threadIdx.x;                   // 128 threads, 1 block
    sm[t] = g_bsum[t];
    __syncthreads();
    int orig = sm[t];
    for (int off = 1; off < 128; off <<= 1) {
        int v = (t >= off) ? sm[t - off] : 0;
        __syncthreads();
        sm[t] += v;
        __syncthreads();
    }
    g_bpre[t] = sm[t] - orig;              // exclusive
    if (t == 127) g_rowptr[N] = E;
}

__global__ void scanC_kernel(int N) {
    __shared__ int sm[256];
    int b = blockIdx.x;                    // 128 blocks of 256
    int chunk = (N + 127) / 128;
    int beg = b * chunk;
    int end = beg + chunk; if (end > N) end = N;
    int sub = (chunk + 255) / 256;
    int t = threadIdx.x;
    int tb = beg + t * sub; if (tb > end) tb = end;
    int te = tb + sub; if (te > end) te = end;
    int s = 0;
    for (int i = tb; i < te; i++) s += g_cnt[i];
    sm[t] = s;
    __syncthreads();
    for (int off = 1; off < 256; off <<= 1) {
        int v = (t >= off) ? sm[t - off] : 0;
        __syncthreads();
        sm[t] += v;
        __syncthreads();
    }
    int run = g_bpre[b] + sm[t] - s;       // exclusive prefix for this thread's range
    for (int i = tb; i < te; i++) {
        g_rowptr[i] = run;
        g_fill[i]   = run;
        run += g_cnt[i];
    }
}

// CSR scatter: NO hashing — pack col + edge id + 25-bit weight into one 8B record.
__global__ void scatter_kernel(const int* __restrict__ index,
                               const float* __restrict__ value, int E,
                               float invkeep, float onemA) {
    int e = blockIdx.x * blockDim.x + threadIdx.x;
    if (e >= E) return;
    int r = index[e];
    unsigned c = (unsigned)index[E + e];
    float wk = onemA * (value[e] * invkeep);   // (1-alpha) * value/keep
    unsigned w32 = __float_as_uint(wk);
    unsigned lo = c | (((unsigned)e & 0x7FFFu) << 17);
    unsigned hi = (w32 & 0xFFFFFF80u) | ((unsigned)e >> 15);   // e < 2^22
    unsigned long long pk = ((unsigned long long)hi << 32) | (unsigned long long)lo;
    int pos = atomicAdd(&g_fill[r], 1);
    g_cw[pos] = pk;
}

// ---------------- fp32 SIMT GEMM with fused dropout, FFMA2 inner loop ----------------
// MODE 0: A = dropout_ka(X) on the fly; epilogue: relu then dropout_kh; -> g_H
// MODE 1: A = g_H; plain epilogue; -> g_Z0 (fp32) AND g_Zh0 (half)
#define BM 64
#define BN 64
#define BK 32
template<int MODE>
__global__ __launch_bounds__(256) void gemm_kernel(const float* __restrict__ Ain,
                                                   const float* __restrict__ W,
                                                   const float* __restrict__ bias,
                                                   int Nrows, int K,
                                                   unsigned ka0, unsigned ka1,
                                                   unsigned kh0, unsigned kh1,
                                                   float invkeep) {
    const float* __restrict__ A = (MODE == 0) ? Ain : g_H;
    float* __restrict__ O       = (MODE == 0) ? g_H : g_Z0;
    __shared__ float As[BM][BK + 1];
    __shared__ float Ws[BK][BN];
    int tid = threadIdx.x;
    int tx = tid & 15, ty = tid >> 4;
    int rowBase = blockIdx.x * BM;
    unsigned long long acc2[4][2];
#pragma unroll
    for (int i = 0; i < 4; i++) { acc2[i][0] = 0ull; acc2[i][1] = 0ull; }

    for (int k0 = 0; k0 < K; k0 += BK) {
#pragma unroll
        for (int l = 0; l < 2; l++) {
            int idx = tid + l * 256;           // A tile 64x32 = 512 float4 slots
            int r = idx >> 3, c4 = idx & 7;
            int gr = rowBase + r;
            float4 v = make_float4(0.f, 0.f, 0.f, 0.f);
            if (gr < Nrows) {
                v = *(const float4*)&A[(size_t)gr * K + k0 + c4 * 4];
                if (MODE == 0) {
                    unsigned eb = (unsigned)gr * (unsigned)K + (unsigned)(k0 + c4 * 4);
                    v.x = tf_keep(tf_bits(ka0, ka1, eb + 0)) ? v.x * invkeep : 0.f;
                    v.y = tf_keep(tf_bits(ka0, ka1, eb + 1)) ? v.y * invkeep : 0.f;
                    v.z = tf_keep(tf_bits(ka0, ka1, eb + 2)) ? v.z * invkeep : 0.f;
                    v.w = tf_keep(tf_bits(ka0, ka1, eb + 3)) ? v.w * invkeep : 0.f;
                }
            }
            As[r][c4 * 4 + 0] = v.x; As[r][c4 * 4 + 1] = v.y;
            As[r][c4 * 4 + 2] = v.z; As[r][c4 * 4 + 3] = v.w;
        }
#pragma unroll
        for (int l = 0; l < 2; l++) {
            int idx = tid + l * 256;           // W tile 32x64
            int r = idx >> 4, c4 = idx & 15;
            float4 v = *(const float4*)&W[(size_t)(k0 + r) * BN + c4 * 4];
            *(float4*)&Ws[r][c4 * 4] = v;
        }
        __syncthreads();
#pragma unroll
        for (int k = 0; k < BK; k++) {
            float4 w = *(float4*)&Ws[k][tx * 4];
            unsigned long long w01 = packf2(w.x, w.y);
            unsigned long long w23 = packf2(w.z, w.w);
#pragma unroll
            for (int i = 0; i < 4; i++) {
                float a = As[ty * 4 + i][k];
                unsigned long long aa = packf2(a, a);
                ffma2(acc2[i][0], aa, w01);
                ffma2(acc2[i][1], aa, w23);
            }
        }
        __syncthreads();
    }
    float4 bv = *(const float4*)&bias[tx * 4];
#pragma unroll
    for (int i = 0; i < 4; i++) {
        int gr = rowBase + ty * 4 + i;
        if (gr < Nrows) {
            float4 o;
            unpackf2(o.x, o.y, acc2[i][0]);
            unpackf2(o.z, o.w, acc2[i][1]);
            o.x += bv.x; o.y += bv.y; o.z += bv.z; o.w += bv.w;
            if (MODE == 0) {
                o.x = fmaxf(o.x, 0.f); o.y = fmaxf(o.y, 0.f);
                o.z = fmaxf(o.z, 0.f); o.w = fmaxf(o.w, 0.f);
                unsigned hb = (unsigned)gr * 64u + (unsigned)(tx * 4);
                o.x = tf_keep(tf_bits(kh0, kh1, hb + 0)) ? o.x * invkeep : 0.f;
                o.y = tf_keep(tf_bits(kh0, kh1, hb + 1)) ? o.y * invkeep : 0.f;
                o.z = tf_keep(tf_bits(kh0, kh1, hb + 2)) ? o.z * invkeep : 0.f;
                o.w = tf_keep(tf_bits(kh0, kh1, hb + 3)) ? o.w * invkeep : 0.f;
            }
            *(float4*)&O[(size_t)gr * BN + tx * 4] = o;
            if (MODE == 1) {
                // half copy for the hop-0 gather
                __half2 h01 = __floats2half2_rn(o.x, o.y);
                __half2 h23 = __floats2half2_rn(o.z, o.w);
                uint2 hp;
                hp.x = *(unsigned*)&h01;
                hp.y = *(unsigned*)&h23;
                *(uint2*)&g_Zh0[(size_t)gr * BN + tx * 4] = hp;
            }
        }
    }
}

// ---------------- propagation hop ----------------
// half Z gather, fp32 accumulate, exact 16^-h scaling.  Edge-dropout mask is
// hashed IN-KERNEL (lane-parallel batches of 16 edges per half-warp + ballot),
// hiding the threefry ALU work under the LTS-bound gather stream.
__global__ __launch_bounds__(256) void hop_kernel(int hop, float* __restrict__ dout,
                                                  int Nrows, float mulA, float mulB,
                                                  unsigned ka, unsigned kb) {
    const __half* __restrict__ Zin =
        (hop == 0) ? g_Zh0 : ((hop & 1) ? g_Zha : g_Zhb);
    __half* __restrict__ Zout = (hop & 1) ? g_Zhb : g_Zha;
    bool isLast = (hop == NUM_HOPS - 1);

    int gw      = (int)((blockIdx.x * (unsigned)blockDim.x + threadIdx.x) >> 5);
    int lane    = threadIdx.x & 31;
    int half_id = lane >> 4;
    int l       = lane & 15;
    int r       = gw * 2 + half_id;

    bool valid = (r < Nrows);
    int s = 0, e_ = 0;
    if (valid) { s = g_rowptr[r]; e_ = g_rowptr[r + 1]; }
    int d = e_ - s;
    int dother = __shfl_xor_sync(0xFFFFFFFFu, d, 16);
    int dmax = d > dother ? d : dother;    // warp-uniform

    float ax = 0.f, ay = 0.f, az = 0.f, aw = 0.f;
    for (int j0 = 0; j0 < dmax; j0 += 16) {
        // batch: lane (half, l) hashes edge s + j0 + l of its half's row
        bool mykeep = false;
        int bj = j0 + l;
        if (bj < d) {
            unsigned long long bpk = __ldg(&g_cw[s + bj]);
            unsigned blo = (unsigned)bpk, bhi = (unsigned)(bpk >> 32);
            unsigned eid = (blo >> 17) | ((bhi & 0x7Fu) << 15);
            mykeep = tf_keep(tf_bits(ka, kb, eid));
        }
        unsigned ball = __ballot_sync(0xFFFFFFFFu, mykeep);
        unsigned myBits = (ball >> (half_id << 4)) & 0xFFFFu;
        int tmax = dmax - j0; if (tmax > 16) tmax = 16;
#pragma unroll 4
        for (int t = 0; t < tmax; t++) {
            int idx = s + j0 + t;
            int cidx = (idx < e_) ? idx : 0;        // clamp (bit t is 0 there)
            unsigned long long pk = __ldg(&g_cw[cidx]);
            unsigned lo = (unsigned)pk;
            unsigned hi = (unsigned)(pk >> 32);
            float ww = ((myBits >> t) & 1u) ? __uint_as_float(hi & 0xFFFFFF80u) : 0.0f;
            uint2 raw = *(const uint2*)&Zin[(size_t)(lo & 0x1FFFFu) * 64 + l * 4];
            float2 z01 = __half22float2(*(const __half2*)&raw.x);
            float2 z23 = __half22float2(*(const __half2*)&raw.y);
            ax = fmaf(ww, z01.x, ax);
            ay = fmaf(ww, z01.y, ay);
            az = fmaf(ww, z23.x, az);
            aw = fmaf(ww, z23.y, aw);
        }
    }
    if (valid) {
        float4 z0 = *(const float4*)&g_Z0[(size_t)r * 64 + l * 4];
        float ox = ax * mulA + mulB * z0.x;
        float oy = ay * mulA + mulB * z0.y;
        float oz = az * mulA + mulB * z0.z;
        float ow = aw * mulA + mulB * z0.w;
        if (isLast) {
            float4 o = make_float4(ox, oy, oz, ow);
            *(float4*)&dout[(size_t)r * 64 + l * 4] = o;
        } else {
            __half2 h01 = __floats2half2_rn(ox, oy);
            __half2 h23 = __floats2half2_rn(oz, ow);
            uint2 hp;
            hp.x = *(unsigned*)&h01;
            hp.y = *(unsigned*)&h23;
            *(uint2*)&Zout[(size_t)r * 64 + l * 4] = hp;
        }
    }
}

// ---------------- host ----------------
extern "C" void kernel_launch(void* const* d_in, const int* in_sizes, int n_in,
                              void* d_out, int out_size) {
    const int*   index = (const int*)d_in[0];
    const float* value = (const float*)d_in[1];
    // Optional scalar "n" may appear as a size-1 input at slot 2.
    int base = (n_in >= 8 && in_sizes[2] == 1) ? 3 : 2;
    const float* X  = (const float*)d_in[base + 0];
    const float* W1 = (const float*)d_in[base + 1];
    const float* b1 = (const float*)d_in[base + 2];
    const float* W2 = (const float*)d_in[base + 3];
    const float* b2 = (const float*)d_in[base + 4];

    int E   = in_sizes[1];
    int HID = in_sizes[base + 2];
    int OUT = in_sizes[base + 4];
    int IN  = in_sizes[base + 1] / HID;
    int N   = in_sizes[base + 0] / IN;
    (void)out_size; (void)OUT;

    // ---- derive JAX keys on host (key(42), fold-like split, fold_in) ----
    unsigned rk0 = 0u, rk1 = 42u;
    unsigned kx0, kx1, kh0, kh1, ke0, ke1;
    tf_block(rk0, rk1, 0u, 0u, kx0, kx1);   // split[0]
    tf_block(rk0, rk1, 0u, 1u, kh0, kh1);   // split[1]
    tf_block(rk0, rk1, 0u, 2u, ke0, ke1);   // split[2]
    unsigned hka[NUM_HOPS], hkb[NUM_HOPS];
    for (unsigned h = 0; h < NUM_HOPS; h++)
        tf_block(ke0, ke1, 0u, h, hka[h], hkb[h]);   // fold_in(ke, h)

    const float invkeep = 1.0f / (1.0f - P_DROP);
    const float onemA   = 1.0f - ALPHA_F;

    const int T = 256;

    // ---- CSR build (scatter no longer hashes) ----
    zero_cnt_kernel<<<(N + T - 1) / T, T>>>(N);
    hist_kernel<<<(E + T - 1) / T, T>>>(index, E);
    scanA_kernel<<<128, 256>>>(N);
    scanB_kernel<<<1, 128>>>(N, E);
    scanC_kernel<<<128, 256>>>(N);
    scatter_kernel<<<(E + T - 1) / T, T>>>(index, value, E, invkeep, onemA);

    // ---- MLP: gemm1 (fused dropout-in + relu + dropout-out) -> gemm2 ----
    gemm_kernel<0><<<(N + BM - 1) / BM, 256>>>(X, W1, b1, N, IN,
                                               kx0, kx1, kh0, kh1, invkeep);
    gemm_kernel<1><<<(N + BM - 1) / BM, 256>>>(X, W2, b2, N, HID,
                                               0u, 0u, 0u, 0u, invkeep);

    // ---- 10 propagation hops, half Z storage with exact 2^-4h scaling ----
    int warpsNeeded = (N + 1) / 2;
    int hopBlocks = (warpsNeeded * 32 + T - 1) / T;
    for (int h = 0; h < NUM_HOPS; h++) {
        float mulA, mulB;
        if (h == NUM_HOPS - 1) {
            mulA = ldexpf(1.0f, 4 * (NUM_HOPS - 1));   // 16^9, exact
            mulB = ALPHA_F;
        } else {
            mulA = 0.0625f;                            // 1/16, exact
            mulB = ALPHA_F * ldexpf(1.0f, -4 * (h + 1));
        }
        hop_kernel<<<hopBlocks, T>>>(h, (float*)d_out, N, mulA, mulB, hka[h], hkb[h]);
    }
}

// round 17
// speedup vs baseline: 1.8742x; 1.2887x over previous
#include <cuda_runtime.h>
#include <cuda_fp16.h>
#include <cstdint>

#define P_DROP   0.1f
#define ALPHA_F  0.1f
#define NUM_HOPS 10

// Fixed problem capacities (N=100000, E=3200000, IN=512, HID=64, OUT=64)
#define MAXN   100352
#define MAXE   3200000
#define MAXNH  6400000    // N*HID / N*OUT

// exact integer form of  (float)((bits>>9) * 2^-23) < 0.9f
#define KEEP_BITS_THRESH 3865470464u

// ---------------- static device scratch (no allocations allowed) ----------------
__device__ float              g_H[MAXNH];
__device__ float              g_Z0[MAXNH];    // fp32 Z0 (alpha anchor + final)
__device__ __half             g_Zh0[MAXNH];   // half Z0 (hop 0 gather input)
__device__ __half             g_Zha[MAXNH];   // ping
__device__ __half             g_Zhb[MAXNH];   // pong
__device__ int                g_cnt[MAXN];
__device__ int                g_rowptr[MAXN + 1];
__device__ int                g_fill[MAXN];
__device__ int                g_bsum[128];
__device__ int                g_bpre[128];
// packed per-CSR-position edge record: lo32 = col | (10-bit hop keep-mask << 22), hi32 = f32 weight
__device__ unsigned long long g_cw[MAXE];

// ---------------- packed f32x2 helpers (Blackwell FFMA2 path, PTX-only) ----------------
__device__ __forceinline__ void ffma2(unsigned long long& d, unsigned long long a,
                                      unsigned long long b) {
    asm("fma.rn.f32x2 %0, %1, %2, %3;" : "=l"(d) : "l"(a), "l"(b), "l"(d));
}
__device__ __forceinline__ unsigned long long packf2(float lo, float hi) {
    unsigned long long r;
    asm("mov.b64 %0, {%1, %2};" : "=l"(r) : "f"(lo), "f"(hi));
    return r;
}
__device__ __forceinline__ void unpackf2(float& lo, float& hi, unsigned long long v) {
    asm("mov.b64 {%0, %1}, %2;" : "=f"(lo), "=f"(hi) : "l"(v));
}

// ---------------- threefry-2x32 (JAX-exact, 20 rounds) ----------------
__host__ __device__ __forceinline__ void tf_block(unsigned k0, unsigned k1,
                                                  unsigned x0, unsigned x1,
                                                  unsigned& o0, unsigned& o1) {
    unsigned k2 = k0 ^ k1 ^ 0x1BD11BDAu;
    x0 += k0; x1 += k1;
#define TF_R(r) { x0 += x1; x1 = (x1 << (r)) | (x1 >> (32 - (r))); x1 ^= x0; }
    TF_R(13) TF_R(15) TF_R(26) TF_R(6)
    x0 += k1; x1 += k2 + 1u;
    TF_R(17) TF_R(29) TF_R(16) TF_R(24)
    x0 += k2; x1 += k0 + 2u;
    TF_R(13) TF_R(15) TF_R(26) TF_R(6)
    x0 += k0; x1 += k1 + 3u;
    TF_R(17) TF_R(29) TF_R(16) TF_R(24)
    x0 += k1; x1 += k2 + 4u;
    TF_R(13) TF_R(15) TF_R(26) TF_R(6)
    x0 += k2; x1 += k0 + 5u;
#undef TF_R
    o0 = x0; o1 = x1;
}

__device__ __forceinline__ unsigned tf_bits(unsigned k0, unsigned k1, unsigned lo) {
    unsigned a, b;
    tf_block(k0, k1, 0u, lo, a, b);
    return a ^ b;
}

__device__ __forceinline__ bool tf_keep(unsigned bits) {
    return bits < KEEP_BITS_THRESH;
}

struct HopKeys { unsigned a[NUM_HOPS]; unsigned b[NUM_HOPS]; };

// ---------------- CSR build ----------------
__global__ void zero_cnt_kernel(int n) {
    int i = blockIdx.x * blockDim.x + threadIdx.x;
    if (i < n) g_cnt[i] = 0;
}

__global__ void hist_kernel(const int* __restrict__ index, int E) {
    int e = blockIdx.x * blockDim.x + threadIdx.x;
    if (e < E) atomicAdd(&g_cnt[index[e]], 1);   // index[0..E) = row
}

// 3-phase parallel exclusive scan of g_cnt -> g_rowptr/g_fill
__global__ void scanA_kernel(int N) {
    __shared__ int red[256];
    int b = blockIdx.x;                    // 128 blocks
    int chunk = (N + 127) / 128;
    int beg = b * chunk;
    int end = beg + chunk; if (end > N) end = N;
    int s = 0;
    for (int i = beg + threadIdx.x; i < end; i += 256) s += g_cnt[i];
    red[threadIdx.x] = s;
    __syncthreads();
    for (int off = 128; off > 0; off >>= 1) {
        if ((int)threadIdx.x < off) red[threadIdx.x] += red[threadIdx.x + off];
        __syncthreads();
    }
    if (threadIdx.x == 0) g_bsum[b] = red[0];
}

__global__ void scanB_kernel(int N, int E) {
    __shared__ int sm[128];
    int t = threadIdx.x;                   // 128 threads, 1 block
    sm[t] = g_bsum[t];
    __syncthreads();
    int orig = sm[t];
    for (int off = 1; off < 128; off <<= 1) {
        int v = (t >= off) ? sm[t - off] : 0;
        __syncthreads();
        sm[t] += v;
        __syncthreads();
    }
    g_bpre[t] = sm[t] - orig;              // exclusive
    if (t == 127) g_rowptr[N] = E;
}

__global__ void scanC_kernel(int N) {
    __shared__ int sm[256];
    int b = blockIdx.x;                    // 128 blocks of 256
    int chunk = (N + 127) / 128;
    int beg = b * chunk;
    int end = beg + chunk; if (end > N) end = N;
    int sub = (chunk + 255) / 256;
    int t = threadIdx.x;
    int tb = beg + t * sub; if (tb > end) tb = end;
    int te = tb + sub; if (te > end) te = end;
    int s = 0;
    for (int i = tb; i < te; i++) s += g_cnt[i];
    sm[t] = s;
    __syncthreads();
    for (int off = 1; off < 256; off <<= 1) {
        int v = (t >= off) ? sm[t - off] : 0;
        __syncthreads();
        sm[t] += v;
        __syncthreads();
    }
    int run = g_bpre[b] + sm[t] - s;       // exclusive prefix for this thread's range
    for (int i = tb; i < te; i++) {
        g_rowptr[i] = run;
        g_fill[i]   = run;
        run += g_cnt[i];
    }
}

// Fused: CSR scatter + 10-hop edge-dropout masks + edge weight, one packed 8B store.
__global__ void scatter_kernel(const int* __restrict__ index,
                               const float* __restrict__ value, int E, HopKeys hk,
                               float invkeep, float onemA) {
    int e = blockIdx.x * blockDim.x + threadIdx.x;
    if (e >= E) return;
    int r = index[e];
    unsigned c = (unsigned)index[E + e];
    unsigned mask = 0;
#pragma unroll
    for (int h = 0; h < NUM_HOPS; h++) {
        unsigned bits = tf_bits(hk.a[h], hk.b[h], (unsigned)e);
        if (tf_keep(bits)) mask |= (1u << h);
    }
    float wk = onemA * (value[e] * invkeep);   // (1-alpha) * value/keep
    unsigned long long pk =
        ((unsigned long long)__float_as_uint(wk) << 32) |
        (unsigned long long)(c | (mask << 22));
    int pos = atomicAdd(&g_fill[r], 1);
    g_cw[pos] = pk;
}

// ---------------- fp32 SIMT GEMM with fused dropout, FFMA2 inner loop ----------------
// MODE 0: A = dropout_ka(X) on the fly; epilogue: relu then dropout_kh; -> g_H
// MODE 1: A = g_H; plain epilogue; -> g_Z0 (fp32) AND g_Zh0 (half)
#define BM 64
#define BN 64
#define BK 32
template<int MODE>
__global__ __launch_bounds__(256) void gemm_kernel(const float* __restrict__ Ain,
                                                   const float* __restrict__ W,
                                                   const float* __restrict__ bias,
                                                   int Nrows, int K,
                                                   unsigned ka0, unsigned ka1,
                                                   unsigned kh0, unsigned kh1,
                                                   float invkeep) {
    const float* __restrict__ A = (MODE == 0) ? Ain : g_H;
    float* __restrict__ O       = (MODE == 0) ? g_H : g_Z0;
    __shared__ float As[BM][BK + 1];
    __shared__ float Ws[BK][BN];
    int tid = threadIdx.x;
    int tx = tid & 15, ty = tid >> 4;
    int rowBase = blockIdx.x * BM;
    unsigned long long acc2[4][2];
#pragma unroll
    for (int i = 0; i < 4; i++) { acc2[i][0] = 0ull; acc2[i][1] = 0ull; }

    for (int k0 = 0; k0 < K; k0 += BK) {
#pragma unroll
        for (int l = 0; l < 2; l++) {
            int idx = tid + l * 256;           // A tile 64x32 = 512 float4 slots
            int r = idx >> 3, c4 = idx & 7;
            int gr = rowBase + r;
            float4 v = make_float4(0.f, 0.f, 0.f, 0.f);
            if (gr < Nrows) {
                v = *(const float4*)&A[(size_t)gr * K + k0 + c4 * 4];
                if (MODE == 0) {
                    unsigned eb = (unsigned)gr * (unsigned)K + (unsigned)(k0 + c4 * 4);
                    v.x = tf_keep(tf_bits(ka0, ka1, eb + 0)) ? v.x * invkeep : 0.f;
                    v.y = tf_keep(tf_bits(ka0, ka1, eb + 1)) ? v.y * invkeep : 0.f;
                    v.z = tf_keep(tf_bits(ka0, ka1, eb + 2)) ? v.z * invkeep : 0.f;
                    v.w = tf_keep(tf_bits(ka0, ka1, eb + 3)) ? v.w * invkeep : 0.f;
                }
            }
            As[r][c4 * 4 + 0] = v.x; As[r][c4 * 4 + 1] = v.y;
            As[r][c4 * 4 + 2] = v.z; As[r][c4 * 4 + 3] = v.w;
        }
#pragma unroll
        for (int l = 0; l < 2; l++) {
            int idx = tid + l * 256;           // W tile 32x64
            int r = idx >> 4, c4 = idx & 15;
            float4 v = *(const float4*)&W[(size_t)(k0 + r) * BN + c4 * 4];
            *(float4*)&Ws[r][c4 * 4] = v;
        }
        __syncthreads();
#pragma unroll
        for (int k = 0; k < BK; k++) {
            float4 w = *(float4*)&Ws[k][tx * 4];
            unsigned long long w01 = packf2(w.x, w.y);
            unsigned long long w23 = packf2(w.z, w.w);
#pragma unroll
            for (int i = 0; i < 4; i++) {
                float a = As[ty * 4 + i][k];
                unsigned long long aa = packf2(a, a);
                ffma2(acc2[i][0], aa, w01);
                ffma2(acc2[i][1], aa, w23);
            }
        }
        __syncthreads();
    }
    float4 bv = *(const float4*)&bias[tx * 4];
#pragma unroll
    for (int i = 0; i < 4; i++) {
        int gr = rowBase + ty * 4 + i;
        if (gr < Nrows) {
            float4 o;
            unpackf2(o.x, o.y, acc2[i][0]);
            unpackf2(o.z, o.w, acc2[i][1]);
            o.x += bv.x; o.y += bv.y; o.z += bv.z; o.w += bv.w;
            if (MODE == 0) {
                o.x = fmaxf(o.x, 0.f); o.y = fmaxf(o.y, 0.f);
                o.z = fmaxf(o.z, 0.f); o.w = fmaxf(o.w, 0.f);
                unsigned hb = (unsigned)gr * 64u + (unsigned)(tx * 4);
                o.x = tf_keep(tf_bits(kh0, kh1, hb + 0)) ? o.x * invkeep : 0.f;
                o.y = tf_keep(tf_bits(kh0, kh1, hb + 1)) ? o.y * invkeep : 0.f;
                o.z = tf_keep(tf_bits(kh0, kh1, hb + 2)) ? o.z * invkeep : 0.f;
                o.w = tf_keep(tf_bits(kh0, kh1, hb + 3)) ? o.w * invkeep : 0.f;
            }
            *(float4*)&O[(size_t)gr * BN + tx * 4] = o;
            if (MODE == 1) {
                // half copy for the hop-0 gather
                __half2 h01 = __floats2half2_rn(o.x, o.y);
                __half2 h23 = __floats2half2_rn(o.z, o.w);
                uint2 hp;
                hp.x = *(unsigned*)&h01;
                hp.y = *(unsigned*)&h23;
                *(uint2*)&g_Zh0[(size_t)gr * BN + tx * 4] = hp;
            }
        }
    }
}

// ---------------- propagation hop: half Z gather, fp32 accumulate, exact 16^-h scaling ----------------
// Branch-free body: dropped edges contribute 0 via ww=0 (exact).  #pragma unroll 4
// lets ptxas front-batch 4 cw loads then 4 Z loads.
__global__ __launch_bounds__(256) void hop_kernel(int hop, float* __restrict__ dout,
                                                  int Nrows, float mulA, float mulB) {
    const __half* __restrict__ Zin =
        (hop == 0) ? g_Zh0 : ((hop & 1) ? g_Zha : g_Zhb);
    __half* __restrict__ Zout = (hop & 1) ? g_Zhb : g_Zha;
    bool isLast = (hop == NUM_HOPS - 1);

    int gw   = (int)((blockIdx.x * (unsigned)blockDim.x + threadIdx.x) >> 5);
    int half_id = (threadIdx.x >> 4) & 1;
    int l    = threadIdx.x & 15;
    int r    = gw * 2 + half_id;

    int s = 0, e = 0;
    if (r < Nrows) { s = g_rowptr[r]; e = g_rowptr[r + 1]; }
    unsigned sh = 22u + (unsigned)hop;
    float ax = 0.f, ay = 0.f, az = 0.f, aw = 0.f;
#pragma unroll 4
    for (int j = s; j < e; j++) {
        unsigned long long pk = __ldg(&g_cw[j]);
        unsigned cw = (unsigned)pk;
        float ww = ((cw >> sh) & 1u) ? __uint_as_float((unsigned)(pk >> 32)) : 0.0f;
        uint2 raw = *(const uint2*)&Zin[(size_t)(cw & 0x3FFFFFu) * 64 + l * 4];
        float2 z01 = __half22float2(*(const __half2*)&raw.x);
        float2 z23 = __half22float2(*(const __half2*)&raw.y);
        ax = fmaf(ww, z01.x, ax);
        ay = fmaf(ww, z01.y, ay);
        az = fmaf(ww, z23.x, az);
        aw = fmaf(ww, z23.y, aw);
    }
    if (r < Nrows) {
        float4 z0 = *(const float4*)&g_Z0[(size_t)r * 64 + l * 4];
        float ox = ax * mulA + mulB * z0.x;
        float oy = ay * mulA + mulB * z0.y;
        float oz = az * mulA + mulB * z0.z;
        float ow = aw * mulA + mulB * z0.w;
        if (isLast) {
            float4 o = make_float4(ox, oy, oz, ow);
            *(float4*)&dout[(size_t)r * 64 + l * 4] = o;
        } else {
            __half2 h01 = __floats2half2_rn(ox, oy);
            __half2 h23 = __floats2half2_rn(oz, ow);
            uint2 hp;
            hp.x = *(unsigned*)&h01;
            hp.y = *(unsigned*)&h23;
            *(uint2*)&Zout[(size_t)r * 64 + l * 4] = hp;
        }
    }
}

// ---------------- host ----------------
extern "C" void kernel_launch(void* const* d_in, const int* in_sizes, int n_in,
                              void* d_out, int out_size) {
    const int*   index = (const int*)d_in[0];
    const float* value = (const float*)d_in[1];
    // Optional scalar "n" may appear as a size-1 input at slot 2.
    int base = (n_in >= 8 && in_sizes[2] == 1) ? 3 : 2;
    const float* X  = (const float*)d_in[base + 0];
    const float* W1 = (const float*)d_in[base + 1];
    const float* b1 = (const float*)d_in[base + 2];
    const float* W2 = (const float*)d_in[base + 3];
    const float* b2 = (const float*)d_in[base + 4];

    int E   = in_sizes[1];
    int HID = in_sizes[base + 2];
    int OUT = in_sizes[base + 4];
    int IN  = in_sizes[base + 1] / HID;
    int N   = in_sizes[base + 0] / IN;
    (void)out_size; (void)OUT;

    // ---- derive JAX keys on host (key(42), fold-like split, fold_in) ----
    unsigned rk0 = 0u, rk1 = 42u;
    unsigned kx0, kx1, kh0, kh1, ke0, ke1;
    tf_block(rk0, rk1, 0u, 0u, kx0, kx1);   // split[0]
    tf_block(rk0, rk1, 0u, 1u, kh0, kh1);   // split[1]
    tf_block(rk0, rk1, 0u, 2u, ke0, ke1);   // split[2]
    HopKeys hk;
    for (unsigned h = 0; h < NUM_HOPS; h++)
        tf_block(ke0, ke1, 0u, h, hk.a[h], hk.b[h]);   // fold_in(ke, h)

    const float invkeep = 1.0f / (1.0f - P_DROP);
    const float onemA   = 1.0f - ALPHA_F;

    const int T = 256;

    // ---- CSR build fused with edge-dropout masks + weights (parallel scan) ----
    zero_cnt_kernel<<<(N + T - 1) / T, T>>>(N);
    hist_kernel<<<(E + T - 1) / T, T>>>(index, E);
    scanA_kernel<<<128, 256>>>(N);
    scanB_kernel<<<1, 128>>>(N, E);
    scanC_kernel<<<128, 256>>>(N);
    scatter_kernel<<<(E + T - 1) / T, T>>>(index, value, E, hk, invkeep, onemA);

    // ---- MLP: gemm1 (fused dropout-in + relu + dropout-out) -> gemm2 ----
    gemm_kernel<0><<<(N + BM - 1) / BM, 256>>>(X, W1, b1, N, IN,
                                               kx0, kx1, kh0, kh1, invkeep);
    gemm_kernel<1><<<(N + BM - 1) / BM, 256>>>(X, W2, b2, N, HID,
                                               0u, 0u, 0u, 0u, invkeep);

    // ---- 10 propagation hops, half Z storage with exact 2^-4h scaling ----
    int warpsNeeded = (N + 1) / 2;
    int hopBlocks = (warpsNeeded * 32 + T - 1) / T;
    for (int h = 0; h < NUM_HOPS; h++) {
        float mulA, mulB;
        if (h == NUM_HOPS - 1) {
            mulA = ldexpf(1.0f, 4 * (NUM_HOPS - 1));   // 16^9, exact
            mulB = ALPHA_F;
        } else {
            mulA = 0.0625f;                            // 1/16, exact
            mulB = ALPHA_F * ldexpf(1.0f, -4 * (h + 1));
        }
        hop_kernel<<<hopBlocks, T>>>(h, (float*)d_out, N, mulA, mulB);
    }
}